// round 11
// baseline (speedup 1.0000x reference)
#include <cuda_runtime.h>
#include <cuda_bf16.h>
#include <cstdint>

#define Nn 20000
#define Ee 320000
#define TN  8

// ---------------- scratch (device globals; no allocation) ----------------
__device__ float g_maggr[Nn * 128];
__device__ float g_paggr[Nn * 128];
__device__ float g_deg[Nn];
__device__ __nv_bfloat16 g_Shi[Nn * 128], g_Slo[Nn * 128];
__device__ __nv_bfloat16 g_W1Thi[128 * 288], g_W1Tlo[128 * 288];
__device__ __nv_bfloat16 g_W2Thi[128 * 128], g_W2Tlo[128 * 128];
__device__ __nv_bfloat16 g_P1Thi[128 * 128], g_P1Tlo[128 * 128];

__constant__ int c_grade[8] = {0, 1, 1, 1, 2, 2, 2, 3};
__device__ constexpr int RES[8][8] = {
    {0,1,2,3,4,5,6,7},{1,0,4,5,2,3,7,6},{2,4,0,6,1,7,3,5},{3,5,6,0,7,1,2,4},
    {4,2,1,7,0,6,5,3},{5,3,7,1,6,0,4,2},{6,7,3,2,5,4,0,1},{7,6,5,4,3,2,1,0}};
__device__ constexpr float SGN[8][8] = {
    { 1, 1, 1, 1, 1, 1, 1, 1},{ 1, 1, 1, 1, 1, 1, 1, 1},
    { 1,-1, 1, 1,-1,-1, 1,-1},{ 1,-1,-1, 1, 1,-1,-1, 1},
    { 1,-1, 1, 1,-1,-1, 1,-1},{ 1,-1,-1, 1, 1,-1,-1, 1},
    { 1, 1,-1, 1,-1, 1,-1,-1},{ 1, 1,-1, 1,-1, 1,-1,-1}};

// ---------------- helpers ----------------
__device__ __forceinline__ uint32_t smem_u32(const void* p) {
    uint32_t a;
    asm("{ .reg .u64 t; cvta.to.shared.u64 t, %1; cvt.u32.u64 %0, t; }" : "=r"(a) : "l"(p));
    return a;
}
// 2 logical 64B rows packed per 128B physical row, SW128 XOR swizzle.
__device__ __forceinline__ uint32_t sw_off(int row, int kb) {
    uint32_t o = ((uint32_t)(row >> 1) << 7) | ((uint32_t)(row & 1) << 6) | (uint32_t)kb;
    return o ^ ((o >> 3) & 0x70);
}
__device__ __forceinline__ void ldsm_x4(uint32_t* r, uint32_t addr) {
    asm volatile("ldmatrix.sync.aligned.m8n8.x4.shared.b16 {%0,%1,%2,%3}, [%4];"
                 : "=r"(r[0]), "=r"(r[1]), "=r"(r[2]), "=r"(r[3]) : "r"(addr));
}
__device__ __forceinline__ void mma16816(float* c, const uint32_t* a, const uint32_t* b) {
    asm volatile("mma.sync.aligned.m16n8k16.row.col.f32.bf16.bf16.f32 "
                 "{%0,%1,%2,%3}, {%4,%5,%6,%7}, {%8,%9}, {%0,%1,%2,%3};"
                 : "+f"(c[0]), "+f"(c[1]), "+f"(c[2]), "+f"(c[3])
                 : "r"(a[0]), "r"(a[1]), "r"(a[2]), "r"(a[3]), "r"(b[0]), "r"(b[1]));
}
__device__ __forceinline__ void cpa16(uint32_t dst, const void* src) {
    asm volatile("cp.async.cg.shared.global [%0], [%1], 16;" :: "r"(dst), "l"(src));
}
#define CP_COMMIT() asm volatile("cp.async.commit_group;" ::: "memory")
#define CP_WAITG(n) asm volatile("cp.async.wait_group %0;" :: "n"(n) : "memory")

// vectorized global float reductions (PTX ISA 8.1+, sm_90+)
__device__ __forceinline__ void red_add_v4(float* p, float x0, float x1, float x2, float x3) {
    asm volatile("red.global.add.v4.f32 [%0], {%1, %2, %3, %4};"
                 :: "l"(p), "f"(x0), "f"(x1), "f"(x2), "f"(x3) : "memory");
}
__device__ __forceinline__ void red_add_v2(float* p, float x0, float x1) {
    asm volatile("red.global.add.v2.f32 [%0], {%1, %2};"
                 :: "l"(p), "f"(x0), "f"(x1) : "memory");
}

__device__ __forceinline__ void split_bf16(float x, __nv_bfloat16& h, __nv_bfloat16& l) {
    h = __float2bfloat16(x);
    l = __float2bfloat16(x - __bfloat162float(h));
}
__device__ __forceinline__ void sm_store2(void* hiP, void* loP, float x0, float x1) {
    union { __nv_bfloat16 b[2]; uint32_t u; } ph, pl;
    split_bf16(x0, ph.b[0], pl.b[0]);
    split_bf16(x1, ph.b[1], pl.b[1]);
    *(uint32_t*)hiP = ph.u;
    *(uint32_t*)loP = pl.u;
}

// ---------------- kernel 0: zero scratch ----------------
__global__ __launch_bounds__(256) void zero_kernel() {
    const int tot = Nn * 128 + Nn * 128 + Nn;
    for (int i = blockIdx.x * blockDim.x + threadIdx.x; i < tot; i += gridDim.x * blockDim.x) {
        if (i < Nn * 128) g_maggr[i] = 0.f;
        else if (i < 2 * Nn * 128) g_paggr[i - Nn * 128] = 0.f;
        else g_deg[i - 2 * Nn * 128] = 0.f;
    }
}

// ---------------- kernel 1: split s + transpose/split weights ----------------
__global__ __launch_bounds__(256) void prep_kernel(
    const float* __restrict__ s, const float* __restrict__ W1,
    const float* __restrict__ W2, const float* __restrict__ P1)
{
    const int R0 = Nn * 128, R1 = 128 * 288, R2 = 128 * 128, R3 = 128 * 128;
    const int T = R0 + R1 + R2 + R3;
    for (int i = blockIdx.x * blockDim.x + threadIdx.x; i < T; i += gridDim.x * blockDim.x) {
        if (i < R0) {
            split_bf16(s[i], g_Shi[i], g_Slo[i]);
        } else if (i < R0 + R1) {
            int j = i - R0, n = j / 288, k = j % 288;
            float w = (k < 272) ? W1[k * 128 + n] : 0.f;
            split_bf16(w, g_W1Thi[j], g_W1Tlo[j]);
        } else if (i < R0 + R1 + R2) {
            int j = i - R0 - R1, n = j >> 7, k = j & 127;
            split_bf16(W2[k * 128 + n], g_W2Thi[j], g_W2Tlo[j]);
        } else {
            int j = i - R0 - R1 - R2, n = j >> 7, k = j & 127;
            split_bf16(P1[k * 128 + n], g_P1Thi[j], g_P1Tlo[j]);
        }
    }
}

// ---------------- fused edge kernel: MVLinear + 3 GEMMs + scatters ----------------
// CTA = 128 edges, 512 threads = 16 warps: rw = w&3 (rows rw*32..+32),
// cw = w>>2 (cols cw*32..+32). acc 32x32 per warp = 32 fp32 regs.
// Prologue: gather v rows -> d (ring, f32) -> edge_attr -> EA smem chunk.
// Phase 1 (K=288, 9 chunks): chunks 0-7 via ring, chunk 8 A = EA smem.
// Phase 2/3: A = sHM; B staged as 2x64-k chunks.
// Phase-3 epilogue: restage d into sHM (dead), recompute vij fp32, scatter.
#define RINGO   0
#define SHMO    98304
#define EAHIO   163840
#define EALOO   172032
#define SP2O    180224
#define SWVO    188416
#define SB1O    192512
#define SB2O    193024
#define SB3O    193536
#define SPB2O   194048
#define SWVBO   194112
#define SSNDO   194176
#define SRCVO   194688
#define FUSED_SMEM 195200

__global__ __launch_bounds__(512, 1) void fused_gemm_kernel(
    const float* __restrict__ v, const int* __restrict__ ei,
    const float* __restrict__ Wv_w, const float* __restrict__ Wv_b,
    const float* __restrict__ b1, const float* __restrict__ b2,
    const float* __restrict__ pb1,
    const float* __restrict__ P2, const float* __restrict__ pb2)
{
    extern __shared__ __align__(128) unsigned char smem[];
    const int tid = threadIdx.x;
    const int lane = tid & 31, w = tid >> 5;
    const int rw = w & 3, cw = w >> 2;
    const int grp = lane >> 2, qid = lane & 3;
    const int e0 = blockIdx.x * 128;
    const uint32_t usm = smem_u32(smem);

    int* ssnd = (int*)(smem + SSNDO);
    int* srcv = (int*)(smem + SRCVO);
    float* sb1 = (float*)(smem + SB1O);
    float* sb2 = (float*)(smem + SB2O);
    float* sb3 = (float*)(smem + SB3O);
    float* sP2 = (float*)(smem + SP2O);
    float* spb2 = (float*)(smem + SPB2O);
    float* swv = (float*)(smem + SWVO);
    float* swvb = (float*)(smem + SWVBO);

    if (tid < 128) {
        int sn = ei[e0 + tid];
        ssnd[tid] = sn;
        srcv[tid] = ei[Ee + e0 + tid];
        sb1[tid] = b1[tid];
        sb2[tid] = b2[tid];
        sb3[tid] = pb1[tid];
        atomicAdd(&g_deg[sn], 1.0f);
    }
    for (int i = tid; i < 2048; i += 512) sP2[i] = P2[i];
    for (int i = tid; i < 1024; i += 512) swv[i] = Wv_w[i];
    if (tid < 16) { spb2[tid] = pb2[tid]; swvb[tid] = Wv_b[tid]; }
    // zero EA buffers (incl. k16-31 pad)
    {
        uint4 z4 = {0u, 0u, 0u, 0u};
        ((uint4*)(smem + EAHIO))[tid] = z4;
        ((uint4*)(smem + EAHIO))[tid + 512] = z4;
    }
    __syncthreads();

    const int er = tid >> 2;        // edge row this thread serves (gather/vij)
    const int eo = tid & 3;         // o-group (4 outputs each)

    // ---- stage d = v[rcv]-v[snd] rows into f32 buffer at dst ----
    auto stage_d = [&](float* dbuf) {
        const float* vs = v + (size_t)ssnd[er] * 128 + eo * 32;
        const float* vr = v + (size_t)srcv[er] * 128 + eo * 32;
        float* drow = dbuf + er * 128 + eo * 32;
        #pragma unroll
        for (int j = 0; j < 8; j++) {
            float4 a = ((const float4*)vr)[j];
            float4 b = ((const float4*)vs)[j];
            float4 d; d.x = a.x - b.x; d.y = a.y - b.y; d.z = a.z - b.z; d.w = a.w - b.w;
            ((float4*)drow)[j] = d;
        }
    };

    // ---- MVLinear accumulation for this thread's (er, o=eo*4..+4), all blades ----
    auto mv_accum = [&](const float* dbuf, float av[4][8]) {
        #pragma unroll
        for (int oo = 0; oo < 4; oo++)
            #pragma unroll
            for (int bl = 0; bl < 8; bl++) av[oo][bl] = 0.f;
        const float* drow = dbuf + er * 128;
        #pragma unroll
        for (int c = 0; c < 16; c++) {
            float4 d0 = ((const float4*)drow)[c * 2];
            float4 d1 = ((const float4*)drow)[c * 2 + 1];
            #pragma unroll
            for (int oo = 0; oo < 4; oo++) {
                const float* wr = swv + (eo * 4 + oo) * 64 + c * 4;
                float w0 = wr[0], w1 = wr[1], w2 = wr[2], w3 = wr[3];
                av[oo][0] += d0.x * w0;
                av[oo][1] += d0.y * w1;
                av[oo][2] += d0.z * w1;
                av[oo][3] += d0.w * w1;
                av[oo][4] += d1.x * w2;
                av[oo][5] += d1.y * w2;
                av[oo][6] += d1.z * w2;
                av[oo][7] += d1.w * w3;
            }
        }
        #pragma unroll
        for (int oo = 0; oo < 4; oo++) av[oo][0] += swvb[eo * 4 + oo];
    };

    // ---- prologue: d -> edge_attr -> EA smem chunk (A-chunk layout) ----
    stage_d((float*)(smem + RINGO));
    __syncthreads();
    {
        float av[4][8];
        mv_accum((float*)(smem + RINGO), av);
        union { __nv_bfloat16 b[4]; uint64_t u; } ph, pl;
        #pragma unroll
        for (int oo = 0; oo < 4; oo++) {
            float ea = 0.f;
            #pragma unroll
            for (int bl = 0; bl < 8; bl++) ea += av[oo][bl] * av[oo][bl];
            split_bf16(ea, ph.b[oo], pl.b[oo]);
        }
        uint32_t off = sw_off(er, (eo >> 1) * 16) + (eo & 1) * 8;
        *(uint64_t*)(smem + EAHIO + off) = ph.u;
        *(uint64_t*)(smem + EALOO + off) = pl.u;
    }
    __syncthreads();

    float acc[2][4][4];

    const int prow = tid >> 2;
    const int pkb = (tid & 3) * 16;

    // phase-1 prefetch: chunk c (A for c<8 + B) into ring stage s
    auto prefetch1 = [&](int c, int s) {
        const uint32_t st = usm + RINGO + s * 32768;
        const uint32_t so = st + sw_off(prow, pkb);
        if (c < 8) {
            int node = (c < 4) ? ssnd[prow] : srcv[prow];
            size_t off = (size_t)node * 128 + (c & 3) * 32;
            cpa16(so, (const char*)(g_Shi + off) + pkb);
            cpa16(so + 8192, (const char*)(g_Slo + off) + pkb);
        }
        size_t o = (size_t)prow * 288 + c * 32;
        cpa16(so + 16384, (const char*)(g_W1Thi + o) + pkb);
        cpa16(so + 24576, (const char*)(g_W1Tlo + o) + pkb);
    };

    // phase-2/3 prefetch: one 64-k B-only chunk into ring stage c
    auto prefetch23 = [&](int phase, int c) {
        const uint32_t st = usm + RINGO + c * 32768;
        const __nv_bfloat16* Whi = (phase == 2) ? g_W2Thi : g_P1Thi;
        const __nv_bfloat16* Wlo = (phase == 2) ? g_W2Tlo : g_P1Tlo;
        #pragma unroll
        for (int sub = 0; sub < 2; sub++) {
            const uint32_t so = st + sub * 16384 + sw_off(prow, pkb);
            size_t o = (size_t)prow * 128 + c * 64 + sub * 32;
            cpa16(so, (const char*)(Whi + o) + pkb);
            cpa16(so + 8192, (const char*)(Wlo + o) + pkb);
        }
    };

    // one 32-k chunk of MMAs (3-pass bf16 split), 32x32 warp tile
    auto chunk_mma = [&](uint32_t aHi, uint32_t aLo, uint32_t bHi, uint32_t bLo) {
        #pragma unroll
        for (int kk = 0; kk < 2; kk++) {
            uint32_t Ahi[2][4], Alo[2][4];
            const int arow = rw * 32 + (lane & 15);
            const int akb = kk * 32 + ((lane >> 4) << 4);
            ldsm_x4(Ahi[0], aHi + sw_off(arow, akb));
            ldsm_x4(Ahi[1], aHi + sw_off(arow + 16, akb));
            ldsm_x4(Alo[0], aLo + sw_off(arow, akb));
            ldsm_x4(Alo[1], aLo + sw_off(arow + 16, akb));
            const int brow0 = cw * 32 + (lane & 7) + ((lane >> 4) << 3);
            const int bkb = kk * 32 + ((lane & 8) ? 16 : 0);
            #pragma unroll
            for (int np = 0; np < 2; np++) {
                uint32_t bh[4], bl[4];
                ldsm_x4(bh, bHi + sw_off(brow0 + np * 16, bkb));
                ldsm_x4(bl, bLo + sw_off(brow0 + np * 16, bkb));
                #pragma unroll
                for (int h2 = 0; h2 < 2; h2++) {
                    const int n = np * 2 + h2;
                    #pragma unroll
                    for (int mt = 0; mt < 2; mt++) {
                        mma16816(acc[mt][n], Ahi[mt], bh + 2 * h2);
                        mma16816(acc[mt][n], Ahi[mt], bl + 2 * h2);
                        mma16816(acc[mt][n], Alo[mt], bh + 2 * h2);
                    }
                }
            }
        }
    };

    auto zero_acc = [&]() {
        #pragma unroll
        for (int mt = 0; mt < 2; mt++)
            #pragma unroll
            for (int n = 0; n < 4; n++)
                #pragma unroll
                for (int q = 0; q < 4; q++) acc[mt][n][q] = 0.f;
    };

    // ================= phase 1 (9 chunks, K=288) =================
    zero_acc();
    prefetch1(0, 0); CP_COMMIT();
    prefetch1(1, 1); CP_COMMIT();
    #pragma unroll 1
    for (int c = 0; c < 9; c++) {
        if (c + 1 < 9) CP_WAITG(1);
        else CP_WAITG(0);
        __syncthreads();
        if (c + 2 < 9) { prefetch1(c + 2, (c + 2) % 3); CP_COMMIT(); }
        const uint32_t st = usm + RINGO + (c % 3) * 32768;
        const uint32_t aHi = (c < 8) ? st : (usm + EAHIO);
        const uint32_t aLo = (c < 8) ? (st + 8192) : (usm + EALOO);
        chunk_mma(aHi, aLo, st + 16384, st + 24576);
    }
    // epilogue: relu + bias -> split -> sHM
    #pragma unroll
    for (int mt = 0; mt < 2; mt++) {
        const int r0 = rw * 32 + mt * 16 + grp;
        #pragma unroll
        for (int n = 0; n < 4; n++) {
            const int cc = cw * 32 + n * 8 + qid * 2;
            const int ch = cc >> 5;
            const uint32_t kb = (uint32_t)(cc & 31) * 2;
            const float bb0 = sb1[cc], bb1 = sb1[cc + 1];
            unsigned char* base = smem + SHMO + ch * 16384;
            uint32_t o0 = sw_off(r0, kb), o1 = sw_off(r0 + 8, kb);
            sm_store2(base + o0, base + 8192 + o0,
                      fmaxf(acc[mt][n][0] + bb0, 0.f), fmaxf(acc[mt][n][1] + bb1, 0.f));
            sm_store2(base + o1, base + 8192 + o1,
                      fmaxf(acc[mt][n][2] + bb0, 0.f), fmaxf(acc[mt][n][3] + bb1, 0.f));
        }
    }
    __syncthreads();

    // ================= phase 2 =================
    zero_acc();
    prefetch23(2, 0); CP_COMMIT();
    prefetch23(2, 1); CP_COMMIT();
    #pragma unroll 1
    for (int c = 0; c < 2; c++) {
        if (c == 0) CP_WAITG(1);
        else CP_WAITG(0);
        __syncthreads();
        const uint32_t st = usm + RINGO + c * 32768;
        #pragma unroll
        for (int sub = 0; sub < 2; sub++) {
            const int s = c * 2 + sub;
            const uint32_t aB = usm + SHMO + s * 16384;
            const uint32_t bB = st + sub * 16384;
            chunk_mma(aB, aB + 8192, bB, bB + 8192);
        }
    }
    __syncthreads();  // all warps done reading sHM before sM overwrites it
    #pragma unroll
    for (int mt = 0; mt < 2; mt++) {
        const int r0 = rw * 32 + mt * 16 + grp;
        const int rA = srcv[r0], rB = srcv[r0 + 8];
        #pragma unroll
        for (int n = 0; n < 4; n++) {
            const int cc = cw * 32 + n * 8 + qid * 2;
            const int ch = cc >> 5;
            const uint32_t kb = (uint32_t)(cc & 31) * 2;
            const float bb0 = sb2[cc], bb1 = sb2[cc + 1];
            float m00 = acc[mt][n][0] + bb0, m01 = acc[mt][n][1] + bb1;
            float m10 = acc[mt][n][2] + bb0, m11 = acc[mt][n][3] + bb1;
            red_add_v2(&g_maggr[(size_t)rA * 128 + cc], m00, m01);
            red_add_v2(&g_maggr[(size_t)rB * 128 + cc], m10, m11);
            unsigned char* base = smem + SHMO + ch * 16384;
            uint32_t o0 = sw_off(r0, kb), o1 = sw_off(r0 + 8, kb);
            sm_store2(base + o0, base + 8192 + o0, m00, m01);
            sm_store2(base + o1, base + 8192 + o1, m10, m11);
        }
    }
    __syncthreads();

    // ================= phase 3 =================
    zero_acc();
    prefetch23(3, 0); CP_COMMIT();
    prefetch23(3, 1); CP_COMMIT();
    #pragma unroll 1
    for (int c = 0; c < 2; c++) {
        if (c == 0) CP_WAITG(1);
        else CP_WAITG(0);
        __syncthreads();
        const uint32_t st = usm + RINGO + c * 32768;
        #pragma unroll
        for (int sub = 0; sub < 2; sub++) {
            const int s = c * 2 + sub;
            const uint32_t aB = usm + SHMO + s * 16384;
            const uint32_t bB = st + sub * 16384;
            chunk_mma(aB, aB + 8192, bB, bB + 8192);
        }
    }
    __syncthreads();  // mma done: ring free for spm, sHM free for d restage
    float* spm = (float*)(smem + RINGO);            // [cw][128][16]
    float* spmT = (float*)(smem + RINGO + 32768);   // [128][16]
    #pragma unroll
    for (int mt = 0; mt < 2; mt++) {
        #pragma unroll
        for (int half = 0; half < 2; half++) {
            const int r = rw * 32 + mt * 16 + grp + half * 8;
            float pm[16];
            #pragma unroll
            for (int o = 0; o < 16; o++) pm[o] = 0.f;
            #pragma unroll
            for (int n = 0; n < 4; n++) {
                const int cc = cw * 32 + n * 8 + qid * 2;
                float x0 = fmaxf(acc[mt][n][half * 2 + 0] + sb3[cc], 0.f);
                float x1 = fmaxf(acc[mt][n][half * 2 + 1] + sb3[cc + 1], 0.f);
                const float* w0 = sP2 + cc * 16;
                const float* w1 = w0 + 16;
                #pragma unroll
                for (int o = 0; o < 16; o++) pm[o] += x0 * w0[o] + x1 * w1[o];
            }
            #pragma unroll
            for (int o = 0; o < 16; o++) {
                pm[o] += __shfl_xor_sync(0xffffffffu, pm[o], 1);
                pm[o] += __shfl_xor_sync(0xffffffffu, pm[o], 2);
            }
            #pragma unroll
            for (int j = 0; j < 4; j++)
                spm[cw * 2048 + r * 16 + qid * 4 + j] = pm[qid * 4 + j];
        }
    }
    // restage d into sHM (dead after phase-3 mma; barrier above covers)
    stage_d((float*)(smem + SHMO));
    __syncthreads();
    #pragma unroll
    for (int j = 0; j < 4; j++) {
        const int e = tid + j * 512;
        const int r = e >> 4, o = e & 15;
        spmT[e] = spm[r * 16 + o] + spm[2048 + r * 16 + o]
                + spm[4096 + r * 16 + o] + spm[6144 + r * 16 + o] + spb2[o];
    }
    __syncthreads();
    // recompute vij (fp32, same math as reference) and scatter pos_m
    {
        float av[4][8];
        mv_accum((float*)(smem + SHMO), av);
        const int rc = srcv[er];
        float* dst = g_paggr + (size_t)rc * 128 + eo * 32;
        #pragma unroll
        for (int oo = 0; oo < 4; oo++) {
            float p = spmT[er * 16 + eo * 4 + oo];
            red_add_v4(dst + oo * 8,
                       av[oo][0] * p, av[oo][1] * p, av[oo][2] * p, av[oo][3] * p);
            red_add_v4(dst + oo * 8 + 4,
                       av[oo][4] * p, av[oo][5] * p, av[oo][6] * p, av[oo][7] * p);
        }
    }
}

// ---------------- kernel: per-node update ----------------
__global__ __launch_bounds__(128) void node_kernel(
    const float* __restrict__ s, const float* __restrict__ v,
    const float* __restrict__ U1, const float* __restrict__ ub1,
    const float* __restrict__ U2, const float* __restrict__ ub2,
    const float* __restrict__ gl_w, const float* __restrict__ gl_b,
    const float* __restrict__ gr_w, const float* __restrict__ gr_b,
    const float* __restrict__ go_w, const float* __restrict__ go_b,
    const float* __restrict__ ln_a,
    float* __restrict__ out_s, float* __restrict__ out_v)
{
    __shared__ __align__(16) float y[TN][256];
    __shared__ __align__(16) float h[TN][128];
    __shared__ __align__(16) float p[TN][128];
    __shared__ __align__(16) float vo[TN][128];
    __shared__ float cn[TN][16];
    __shared__ float nrm[TN];
    __shared__ float dinv[TN];
    __shared__ float wl[1024], wr[1024], wo[2048];
    __shared__ float wlb[16], wrb[16], wob[16], lna[16];

    const int tid = threadIdx.x;
    const int n0 = blockIdx.x * TN;

    for (int i = tid; i < 1024; i += 128) { wl[i] = gl_w[i]; wr[i] = gr_w[i]; }
    for (int i = tid; i < 2048; i += 128) wo[i] = go_w[i];
    if (tid < 16) { wlb[tid] = gl_b[tid]; wrb[tid] = gr_b[tid];
                    wob[tid] = go_b[tid]; lna[tid] = ln_a[tid]; }
    if (tid < TN) dinv[tid] = rsqrtf(g_deg[n0 + tid]);
    __syncthreads();

    for (int idx = tid; idx < TN * 128; idx += 128) {
        int n = idx >> 7, c = idx & 127;
        y[n][c]       = s[(n0 + n) * 128 + c];
        y[n][128 + c] = g_maggr[(n0 + n) * 128 + c] * dinv[n];
        p[n][c]       = g_paggr[(n0 + n) * 128 + c] * dinv[n];
    }
    __syncthreads();

    {
        float acc[TN];
        float bb = ub1[tid];
        #pragma unroll
        for (int n = 0; n < TN; n++) acc[n] = bb;
        for (int k = 0; k < 256; k += 4) {
            float w0 = U1[(k + 0) * 128 + tid];
            float w1 = U1[(k + 1) * 128 + tid];
            float w2 = U1[(k + 2) * 128 + tid];
            float w3 = U1[(k + 3) * 128 + tid];
            #pragma unroll
            for (int n = 0; n < TN; n++) {
                float4 x = *(const float4*)&y[n][k];
                acc[n] += x.x * w0 + x.y * w1 + x.z * w2 + x.w * w3;
            }
        }
        #pragma unroll
        for (int n = 0; n < TN; n++) h[n][tid] = fmaxf(acc[n], 0.f);
    }
    __syncthreads();

    {
        float acc[TN];
        float bb = ub2[tid];
        #pragma unroll
        for (int n = 0; n < TN; n++) acc[n] = bb;
        for (int k = 0; k < 128; k += 4) {
            float w0 = U2[(k + 0) * 128 + tid];
            float w1 = U2[(k + 1) * 128 + tid];
            float w2 = U2[(k + 2) * 128 + tid];
            float w3 = U2[(k + 3) * 128 + tid];
            #pragma unroll
            for (int n = 0; n < TN; n++) {
                float4 x = *(const float4*)&h[n][k];
                acc[n] += x.x * w0 + x.y * w1 + x.z * w2 + x.w * w3;
            }
        }
        #pragma unroll
        for (int n = 0; n < TN; n++)
            out_s[(n0 + n) * 128 + tid] = y[n][tid] + acc[n];
    }
    __syncthreads();

    for (int idx = tid; idx < TN * 128; idx += 128) {
        int n = idx >> 7, z = idx & 127, o = z >> 3, bl = z & 7;
        int g = c_grade[bl];
        float al = (bl == 0) ? wlb[o] : 0.f;
        float ar = (bl == 0) ? wrb[o] : 0.f;
        #pragma unroll
        for (int c = 0; c < 16; c++) {
            float pv = p[n][c * 8 + bl];
            al += pv * wl[o * 64 + c * 4 + g];
            ar += pv * wr[o * 64 + c * 4 + g];
        }
        y[n][z] = al;
        y[n][128 + z] = ar;
    }
    __syncthreads();

    for (int idx = tid; idx < TN * 16; idx += 128) {
        int n = idx >> 4, c = idx & 15;
        float a[8], b[8], o8[8];
        #pragma unroll
        for (int i = 0; i < 8; i++) {
            a[i] = y[n][c * 8 + i];
            b[i] = y[n][128 + c * 8 + i];
            o8[i] = 0.f;
        }
        #pragma unroll
        for (int i = 0; i < 8; i++)
            #pragma unroll
            for (int j = 0; j < 8; j++)
                o8[RES[i][j]] += SGN[i][j] * a[i] * b[j];
        #pragma unroll
        for (int k = 0; k < 8; k++) h[n][c * 8 + k] = o8[k];
    }
    __syncthreads();

    for (int idx = tid; idx < TN * 128; idx += 128) {
        int n = idx >> 7, z = idx & 127, o = z >> 3, bl = z & 7;
        int g = c_grade[bl];
        float acc = (bl == 0) ? wob[o] : 0.f;
        #pragma unroll
        for (int c = 0; c < 16; c++)
            acc += h[n][c * 8 + bl] * wo[o * 128 + c * 4 + g];
        #pragma unroll
        for (int c = 0; c < 16; c++)
            acc += p[n][c * 8 + bl] * wo[o * 128 + (16 + c) * 4 + g];
        vo[n][z] = acc;
    }
    __syncthreads();

    for (int idx = tid; idx < TN * 16; idx += 128) {
        int n = idx >> 4, c = idx & 15;
        float acc = 0.f;
        #pragma unroll
        for (int bl = 0; bl < 8; bl++) { float x = vo[n][c * 8 + bl]; acc += x * x; }
        cn[n][c] = sqrtf(acc);
    }
    __syncthreads();
    if (tid < TN) {
        float acc = 0.f;
        #pragma unroll
        for (int c = 0; c < 16; c++) acc += cn[tid][c];
        nrm[tid] = acc * (1.f / 16.f) + 1e-6f;
    }
    __syncthreads();
    for (int idx = tid; idx < TN * 128; idx += 128) {
        int n = idx >> 7, z = idx & 127, c = z >> 3;
        out_v[(n0 + n) * 128 + z] = lna[c] * vo[n][z] / nrm[n] + v[(n0 + n) * 128 + z];
    }
}

// ---------------- launcher ----------------
extern "C" void kernel_launch(void* const* d_in, const int* in_sizes, int n_in,
                              void* d_out, int out_size) {
    const float* s     = (const float*)d_in[0];
    const float* v     = (const float*)d_in[1];
    const int*   ei    = (const int*)  d_in[2];
    const float* Wv_w  = (const float*)d_in[3];
    const float* Wv_b  = (const float*)d_in[4];
    const float* mn_W1 = (const float*)d_in[5];
    const float* mn_b1 = (const float*)d_in[6];
    const float* mn_W2 = (const float*)d_in[7];
    const float* mn_b2 = (const float*)d_in[8];
    const float* pn_W1 = (const float*)d_in[9];
    const float* pn_b1 = (const float*)d_in[10];
    const float* pn_W2 = (const float*)d_in[11];
    const float* pn_b2 = (const float*)d_in[12];
    const float* un_W1 = (const float*)d_in[13];
    const float* un_b1 = (const float*)d_in[14];
    const float* un_W2 = (const float*)d_in[15];
    const float* un_b2 = (const float*)d_in[16];
    const float* gl_w  = (const float*)d_in[17];
    const float* gl_b  = (const float*)d_in[18];
    const float* gr_w  = (const float*)d_in[19];
    const float* gr_b  = (const float*)d_in[20];
    const float* go_w  = (const float*)d_in[21];
    const float* go_b  = (const float*)d_in[22];
    const float* ln_a  = (const float*)d_in[23];
    float* out = (float*)d_out;

    cudaFuncSetAttribute(fused_gemm_kernel,
                         cudaFuncAttributeMaxDynamicSharedMemorySize, FUSED_SMEM);

    zero_kernel<<<2048, 256>>>();
    prep_kernel<<<2048, 256>>>(s, mn_W1, mn_W2, pn_W1);
    fused_gemm_kernel<<<Ee / 128, 512, FUSED_SMEM>>>(
        v, ei, Wv_w, Wv_b, mn_b1, mn_b2, pn_b1, pn_W2, pn_b2);
    node_kernel<<<Nn / TN, 128>>>(s, v, un_W1, un_b1, un_W2, un_b2,
                                  gl_w, gl_b, gr_w, gr_b, go_w, go_b, ln_a,
                                  out, out + Nn * 128);
}

// round 13
// speedup vs baseline: 1.2686x; 1.2686x over previous
#include <cuda_runtime.h>
#include <cuda_bf16.h>
#include <cstdint>

#define Nn 20000
#define Ee 320000
#define TBE 16
#define TN  8

// ---------------- scratch (device globals; no allocation) ----------------
__device__ float g_maggr[Nn * 128];
__device__ float g_paggr[Nn * 128];
__device__ float g_deg[Nn];
__device__ float g_vij[(size_t)Ee * 128];
__device__ __nv_bfloat16 g_Shi[Nn * 128], g_Slo[Nn * 128];
__device__ __nv_bfloat16 g_EAhi[(size_t)Ee * 64], g_EAlo[(size_t)Ee * 64];
__device__ __nv_bfloat16 g_W1Thi[128 * 320], g_W1Tlo[128 * 320];
__device__ __nv_bfloat16 g_W2Thi[128 * 128], g_W2Tlo[128 * 128];
__device__ __nv_bfloat16 g_P1Thi[128 * 128], g_P1Tlo[128 * 128];

__constant__ int c_grade[8] = {0, 1, 1, 1, 2, 2, 2, 3};
__device__ constexpr int RES[8][8] = {
    {0,1,2,3,4,5,6,7},{1,0,4,5,2,3,7,6},{2,4,0,6,1,7,3,5},{3,5,6,0,7,1,2,4},
    {4,2,1,7,0,6,5,3},{5,3,7,1,6,0,4,2},{6,7,3,2,5,4,0,1},{7,6,5,4,3,2,1,0}};
__device__ constexpr float SGN[8][8] = {
    { 1, 1, 1, 1, 1, 1, 1, 1},{ 1, 1, 1, 1, 1, 1, 1, 1},
    { 1,-1, 1, 1,-1,-1, 1,-1},{ 1,-1,-1, 1, 1,-1,-1, 1},
    { 1,-1, 1, 1,-1,-1, 1,-1},{ 1,-1,-1, 1, 1,-1,-1, 1},
    { 1, 1,-1, 1,-1, 1,-1,-1},{ 1, 1,-1, 1,-1, 1,-1,-1}};

// ---------------- helpers ----------------
__device__ __forceinline__ uint32_t smem_u32(const void* p) {
    uint32_t a;
    asm("{ .reg .u64 t; cvta.to.shared.u64 t, %1; cvt.u32.u64 %0, t; }" : "=r"(a) : "l"(p));
    return a;
}
// 2 logical 64B rows packed per 128B physical row, SW128 XOR swizzle.
__device__ __forceinline__ uint32_t sw_off(int row, int kb) {
    uint32_t o = ((uint32_t)(row >> 1) << 7) | ((uint32_t)(row & 1) << 6) | (uint32_t)kb;
    return o ^ ((o >> 3) & 0x70);
}
__device__ __forceinline__ void ldsm_x4(uint32_t* r, uint32_t addr) {
    asm volatile("ldmatrix.sync.aligned.m8n8.x4.shared.b16 {%0,%1,%2,%3}, [%4];"
                 : "=r"(r[0]), "=r"(r[1]), "=r"(r[2]), "=r"(r[3]) : "r"(addr));
}
__device__ __forceinline__ void mma16816(float* c, const uint32_t* a, const uint32_t* b) {
    asm volatile("mma.sync.aligned.m16n8k16.row.col.f32.bf16.bf16.f32 "
                 "{%0,%1,%2,%3}, {%4,%5,%6,%7}, {%8,%9}, {%0,%1,%2,%3};"
                 : "+f"(c[0]), "+f"(c[1]), "+f"(c[2]), "+f"(c[3])
                 : "r"(a[0]), "r"(a[1]), "r"(a[2]), "r"(a[3]), "r"(b[0]), "r"(b[1]));
}
__device__ __forceinline__ void cpa16(uint32_t dst, const void* src) {
    asm volatile("cp.async.cg.shared.global [%0], [%1], 16;" :: "r"(dst), "l"(src));
}
#define CP_COMMIT() asm volatile("cp.async.commit_group;" ::: "memory")
#define CP_WAITG(n) asm volatile("cp.async.wait_group %0;" :: "n"(n) : "memory")

// vectorized global float reductions (PTX ISA 8.1+, sm_90+)
__device__ __forceinline__ void red_add_v4(float* p, float x0, float x1, float x2, float x3) {
    asm volatile("red.global.add.v4.f32 [%0], {%1, %2, %3, %4};"
                 :: "l"(p), "f"(x0), "f"(x1), "f"(x2), "f"(x3) : "memory");
}
__device__ __forceinline__ void red_add_v2(float* p, float x0, float x1) {
    asm volatile("red.global.add.v2.f32 [%0], {%1, %2};"
                 :: "l"(p), "f"(x0), "f"(x1) : "memory");
}

__device__ __forceinline__ void split_bf16(float x, __nv_bfloat16& h, __nv_bfloat16& l) {
    h = __float2bfloat16(x);
    l = __float2bfloat16(x - __bfloat162float(h));
}
__device__ __forceinline__ void sm_store2(void* hiP, void* loP, float x0, float x1) {
    union { __nv_bfloat16 b[2]; uint32_t u; } ph, pl;
    split_bf16(x0, ph.b[0], pl.b[0]);
    split_bf16(x1, ph.b[1], pl.b[1]);
    *(uint32_t*)hiP = ph.u;
    *(uint32_t*)loP = pl.u;
}

// ---------------- kernel 0: zero scratch ----------------
__global__ __launch_bounds__(256) void zero_kernel() {
    const int tot = Nn * 128 + Nn * 128 + Nn;
    for (int i = blockIdx.x * blockDim.x + threadIdx.x; i < tot; i += gridDim.x * blockDim.x) {
        if (i < Nn * 128) g_maggr[i] = 0.f;
        else if (i < 2 * Nn * 128) g_paggr[i - Nn * 128] = 0.f;
        else g_deg[i - 2 * Nn * 128] = 0.f;
    }
}

// ---------------- kernel 1: split s + transpose/split weights ----------------
__global__ __launch_bounds__(256) void prep_kernel(
    const float* __restrict__ s, const float* __restrict__ W1,
    const float* __restrict__ W2, const float* __restrict__ P1)
{
    const int R0 = Nn * 128, R1 = 128 * 320, R2 = 128 * 128, R3 = 128 * 128;
    const int T = R0 + R1 + R2 + R3;
    for (int i = blockIdx.x * blockDim.x + threadIdx.x; i < T; i += gridDim.x * blockDim.x) {
        if (i < R0) {
            split_bf16(s[i], g_Shi[i], g_Slo[i]);
        } else if (i < R0 + R1) {
            int j = i - R0, n = j / 320, k = j % 320;
            float w = (k < 272) ? W1[k * 128 + n] : 0.f;
            split_bf16(w, g_W1Thi[j], g_W1Tlo[j]);
        } else if (i < R0 + R1 + R2) {
            int j = i - R0 - R1, n = j >> 7, k = j & 127;
            split_bf16(W2[k * 128 + n], g_W2Thi[j], g_W2Tlo[j]);
        } else {
            int j = i - R0 - R1 - R2, n = j >> 7, k = j & 127;
            split_bf16(P1[k * 128 + n], g_P1Thi[j], g_P1Tlo[j]);
        }
    }
}

// ---------------- kernel 2: per-edge MVLinear + edge_attr ----------------
__global__ __launch_bounds__(128) void edge_pre_kernel(
    const float* __restrict__ v, const int* __restrict__ ei,
    const float* __restrict__ Wv_w, const float* __restrict__ Wv_b)
{
    __shared__ float bufA[TBE][128];
    __shared__ float vij[TBE][128];
    __shared__ float attr[TBE][16];
    __shared__ float wv[1024], wvb[16];
    __shared__ int snd[TBE], rcv[TBE];

    const int tid = threadIdx.x;
    const int e0 = blockIdx.x * TBE;

    if (tid < TBE) { snd[tid] = ei[e0 + tid]; rcv[tid] = ei[Ee + e0 + tid]; }
    for (int i = tid; i < 1024; i += 128) wv[i] = Wv_w[i];
    if (tid < 16) wvb[tid] = Wv_b[tid];
    __syncthreads();

    for (int idx = tid; idx < TBE * 128; idx += 128) {
        int e = idx >> 7, z = idx & 127;
        bufA[e][z] = v[rcv[e] * 128 + z] - v[snd[e] * 128 + z];
    }
    if (tid < TBE) atomicAdd(&g_deg[snd[tid]], 1.0f);
    __syncthreads();

    for (int idx = tid; idx < TBE * 128; idx += 128) {
        int e = idx >> 7, z = idx & 127, o = z >> 3, bl = z & 7;
        int g = c_grade[bl];
        float acc = (bl == 0) ? wvb[o] : 0.f;
        #pragma unroll
        for (int c = 0; c < 16; c++) acc += bufA[e][c * 8 + bl] * wv[o * 64 + c * 4 + g];
        vij[e][z] = acc;
    }
    __syncthreads();

    for (int idx = tid; idx < TBE * 16; idx += 128) {
        int e = idx >> 4, o = idx & 15;
        float acc = 0.f;
        #pragma unroll
        for (int bl = 0; bl < 8; bl++) { float x = vij[e][o * 8 + bl]; acc += x * x; }
        attr[e][o] = acc;
    }
    __syncthreads();

    for (int idx = tid; idx < TBE * 128; idx += 128) {
        int e = idx >> 7, z = idx & 127;
        g_vij[(size_t)(e0 + e) * 128 + z] = vij[e][z];
    }
    for (int idx = tid; idx < TBE * 64; idx += 128) {
        int e = idx >> 6, z = idx & 63;
        float x = (z < 16) ? attr[e][z] : 0.f;
        __nv_bfloat16 h, l; split_bf16(x, h, l);
        g_EAhi[(size_t)(e0 + e) * 64 + z] = h;
        g_EAlo[(size_t)(e0 + e) * 64 + z] = l;
    }
}

// ---------------- fused 3-GEMM edge kernel (M=64 tile, 2 CTAs/SM) ----------------
// CTA = 64 edges, 256 threads = 8 warps: rw = w&1 (rows rw*32..+32),
// cw = w>>1 (cols cw*32..+32). acc 32x32 per warp = 32 fp32 regs.
// 2-stage ring (24KB/stage: [Ahi 4K|Alo 4K|Bhi 8K|Blo 8K]); per-chunk order
// wait(0) -> sync -> prefetch(c+1) -> mma(c) (prefetch lands in stage(c-1),
// safe: the sync proved all warps finished mma(c-1)).
#define RINGO   0
#define SHMO    49152
#define SP2O    81920
#define SB1O    90112
#define SB2O    90624
#define SB3O    91136
#define SPB2O   91648
#define SSNDO   91712
#define SRCVO   91968
#define FUSED_SMEM 92224

__global__ __launch_bounds__(256, 2) void fused_gemm_kernel(
    const int* __restrict__ ei, const float* __restrict__ b1,
    const float* __restrict__ b2, const float* __restrict__ pb1,
    const float* __restrict__ P2, const float* __restrict__ pb2)
{
    extern __shared__ __align__(128) unsigned char smem[];
    const int tid = threadIdx.x;
    const int lane = tid & 31, w = tid >> 5;
    const int rw = w & 1, cw = w >> 1;
    const int grp = lane >> 2, qid = lane & 3;
    const int e0 = blockIdx.x * 64;
    const uint32_t usm = smem_u32(smem);

    int* ssnd = (int*)(smem + SSNDO);
    int* srcv = (int*)(smem + SRCVO);
    float* sb1 = (float*)(smem + SB1O);
    float* sb2 = (float*)(smem + SB2O);
    float* sb3 = (float*)(smem + SB3O);
    float* sP2 = (float*)(smem + SP2O);
    float* spb2 = (float*)(smem + SPB2O);

    if (tid < 64) {
        ssnd[tid] = ei[e0 + tid];
        srcv[tid] = ei[Ee + e0 + tid];
    }
    if (tid < 128) {
        sb1[tid] = b1[tid];
        sb2[tid] = b2[tid];
        sb3[tid] = pb1[tid];
    }
    for (int i = tid; i < 2048; i += 256) sP2[i] = P2[i];
    if (tid < 16) spb2[tid] = pb2[tid];
    __syncthreads();

    float acc[2][4][4];

    const int prow = tid >> 2;          // A row 0..63
    const int pkb = (tid & 3) * 16;     // byte offset in 64B row
    const int brow = tid >> 1;          // B row 0..127
    const int bkb = (tid & 1) * 32;     // byte offset (2x 16B each)

    // phase-1 prefetch: chunk c of K=320 into ring stage s
    auto prefetch1 = [&](int c, int s) {
        const uint32_t st = usm + RINGO + s * 24576;
        const uint32_t so = st + sw_off(prow, pkb);
        if (c < 8) {
            int node = (c < 4) ? ssnd[prow] : srcv[prow];
            size_t off = (size_t)node * 128 + (c & 3) * 32;
            cpa16(so, (const char*)(g_Shi + off) + pkb);
            cpa16(so + 4096, (const char*)(g_Slo + off) + pkb);
        } else {
            size_t off = (size_t)(e0 + prow) * 64 + (c - 8) * 32;
            cpa16(so, (const char*)(g_EAhi + off) + pkb);
            cpa16(so + 4096, (const char*)(g_EAlo + off) + pkb);
        }
        size_t o = (size_t)brow * 320 + c * 32;
        const char* bh = (const char*)(g_W1Thi + o);
        const char* bl = (const char*)(g_W1Tlo + o);
        uint32_t d0 = st + 8192 + sw_off(brow, bkb);
        uint32_t d1 = st + 8192 + sw_off(brow, bkb + 16);
        cpa16(d0, bh + bkb);
        cpa16(d1, bh + bkb + 16);
        cpa16(d0 + 8192, bl + bkb);
        cpa16(d1 + 8192, bl + bkb + 16);
    };

    // phase-2/3 prefetch: 32-k B-only chunk into ring stage s
    auto prefetch23 = [&](int phase, int c, int s) {
        const uint32_t st = usm + RINGO + s * 24576;
        const __nv_bfloat16* Whi = (phase == 2) ? g_W2Thi : g_P1Thi;
        const __nv_bfloat16* Wlo = (phase == 2) ? g_W2Tlo : g_P1Tlo;
        size_t o = (size_t)brow * 128 + c * 32;
        uint32_t d0 = st + sw_off(brow, bkb);
        uint32_t d1 = st + sw_off(brow, bkb + 16);
        cpa16(d0, (const char*)(Whi + o) + bkb);
        cpa16(d1, (const char*)(Whi + o) + bkb + 16);
        cpa16(d0 + 8192, (const char*)(Wlo + o) + bkb);
        cpa16(d1 + 8192, (const char*)(Wlo + o) + bkb + 16);
    };

    // one 32-k chunk of MMAs (3-pass bf16 split), 32x32 warp tile
    auto chunk_mma = [&](uint32_t aHi, uint32_t aLo, uint32_t bHi, uint32_t bLo) {
        #pragma unroll
        for (int kk = 0; kk < 2; kk++) {
            uint32_t Ahi[2][4], Alo[2][4];
            const int arow = rw * 32 + (lane & 15);
            const int akb = kk * 32 + ((lane >> 4) << 4);
            ldsm_x4(Ahi[0], aHi + sw_off(arow, akb));
            ldsm_x4(Ahi[1], aHi + sw_off(arow + 16, akb));
            ldsm_x4(Alo[0], aLo + sw_off(arow, akb));
            ldsm_x4(Alo[1], aLo + sw_off(arow + 16, akb));
            const int brow0 = cw * 32 + (lane & 7) + ((lane >> 4) << 3);
            const int bkb2 = kk * 32 + ((lane & 8) ? 16 : 0);
            #pragma unroll
            for (int np = 0; np < 2; np++) {
                uint32_t bh[4], bl[4];
                ldsm_x4(bh, bHi + sw_off(brow0 + np * 16, bkb2));
                ldsm_x4(bl, bLo + sw_off(brow0 + np * 16, bkb2));
                #pragma unroll
                for (int h2 = 0; h2 < 2; h2++) {
                    const int n = np * 2 + h2;
                    #pragma unroll
                    for (int mt = 0; mt < 2; mt++) {
                        mma16816(acc[mt][n], Ahi[mt], bh + 2 * h2);
                        mma16816(acc[mt][n], Ahi[mt], bl + 2 * h2);
                        mma16816(acc[mt][n], Alo[mt], bh + 2 * h2);
                    }
                }
            }
        }
    };

    auto zero_acc = [&]() {
        #pragma unroll
        for (int mt = 0; mt < 2; mt++)
            #pragma unroll
            for (int n = 0; n < 4; n++)
                #pragma unroll
                for (int q = 0; q < 4; q++) acc[mt][n][q] = 0.f;
    };

    // ================= phase 1 (10 chunks, K=320) =================
    zero_acc();
    prefetch1(0, 0); CP_COMMIT();
    #pragma unroll 1
    for (int c = 0; c < 10; c++) {
        CP_WAITG(0);
        __syncthreads();   // chunk c visible; all warps done mma(c-1)
        if (c + 1 < 10) { prefetch1(c + 1, (c + 1) & 1); CP_COMMIT(); }
        const uint32_t st = usm + RINGO + (c & 1) * 24576;
        chunk_mma(st, st + 4096, st + 8192, st + 16384);
    }
    // epilogue: relu + bias -> split -> sHM (4 chunks of 8KB: hi @0, lo @4096)
    #pragma unroll
    for (int mt = 0; mt < 2; mt++) {
        const int r0 = rw * 32 + mt * 16 + grp;
        #pragma unroll
        for (int n = 0; n < 4; n++) {
            const int cc = cw * 32 + n * 8 + qid * 2;
            const int ch = cc >> 5;
            const uint32_t kb = (uint32_t)(cc & 31) * 2;
            const float bb0 = sb1[cc], bb1 = sb1[cc + 1];
            unsigned char* base = smem + SHMO + ch * 8192;
            uint32_t o0 = sw_off(r0, kb), o1 = sw_off(r0 + 8, kb);
            sm_store2(base + o0, base + 4096 + o0,
                      fmaxf(acc[mt][n][0] + bb0, 0.f), fmaxf(acc[mt][n][1] + bb1, 0.f));
            sm_store2(base + o1, base + 4096 + o1,
                      fmaxf(acc[mt][n][2] + bb0, 0.f), fmaxf(acc[mt][n][3] + bb1, 0.f));
        }
    }
    __syncthreads();

    // ================= phase 2 (4 chunks, K=128) =================
    zero_acc();
    prefetch23(2, 0, 0); CP_COMMIT();
    #pragma unroll 1
    for (int c = 0; c < 4; c++) {
        CP_WAITG(0);
        __syncthreads();
        if (c + 1 < 4) { prefetch23(2, c + 1, (c + 1) & 1); CP_COMMIT(); }
        const uint32_t st = usm + RINGO + (c & 1) * 24576;
        const uint32_t aB = usm + SHMO + c * 8192;
        chunk_mma(aB, aB + 4096, st, st + 8192);
    }
    __syncthreads();  // all warps done reading sHM before sM overwrites it
    #pragma unroll
    for (int mt = 0; mt < 2; mt++) {
        const int r0 = rw * 32 + mt * 16 + grp;
        const int rA = srcv[r0], rB = srcv[r0 + 8];
        #pragma unroll
        for (int n = 0; n < 4; n++) {
            const int cc = cw * 32 + n * 8 + qid * 2;
            const int ch = cc >> 5;
            const uint32_t kb = (uint32_t)(cc & 31) * 2;
            const float bb0 = sb2[cc], bb1 = sb2[cc + 1];
            float m00 = acc[mt][n][0] + bb0, m01 = acc[mt][n][1] + bb1;
            float m10 = acc[mt][n][2] + bb0, m11 = acc[mt][n][3] + bb1;
            red_add_v2(&g_maggr[(size_t)rA * 128 + cc], m00, m01);
            red_add_v2(&g_maggr[(size_t)rB * 128 + cc], m10, m11);
            unsigned char* base = smem + SHMO + ch * 8192;
            uint32_t o0 = sw_off(r0, kb), o1 = sw_off(r0 + 8, kb);
            sm_store2(base + o0, base + 4096 + o0, m00, m01);
            sm_store2(base + o1, base + 4096 + o1, m10, m11);
        }
    }
    __syncthreads();

    // ================= phase 3 (4 chunks, K=128) =================
    zero_acc();
    prefetch23(3, 0, 0); CP_COMMIT();
    #pragma unroll 1
    for (int c = 0; c < 4; c++) {
        CP_WAITG(0);
        __syncthreads();
        if (c + 1 < 4) { prefetch23(3, c + 1, (c + 1) & 1); CP_COMMIT(); }
        const uint32_t st = usm + RINGO + (c & 1) * 24576;
        const uint32_t aB = usm + SHMO + c * 8192;
        chunk_mma(aB, aB + 4096, st, st + 8192);
    }
    __syncthreads();  // ring free for spm
    float* spm = (float*)(smem + RINGO);            // [cw][64][16] = 16KB
    float* spmT = (float*)(smem + RINGO + 16384);   // [64][16] = 4KB
    #pragma unroll
    for (int mt = 0; mt < 2; mt++) {
        #pragma unroll
        for (int half = 0; half < 2; half++) {
            const int r = rw * 32 + mt * 16 + grp + half * 8;
            float pm[16];
            #pragma unroll
            for (int o = 0; o < 16; o++) pm[o] = 0.f;
            #pragma unroll
            for (int n = 0; n < 4; n++) {
                const int cc = cw * 32 + n * 8 + qid * 2;
                float x0 = fmaxf(acc[mt][n][half * 2 + 0] + sb3[cc], 0.f);
                float x1 = fmaxf(acc[mt][n][half * 2 + 1] + sb3[cc + 1], 0.f);
                const float* w0 = sP2 + cc * 16;
                const float* w1 = w0 + 16;
                #pragma unroll
                for (int o = 0; o < 16; o++) pm[o] += x0 * w0[o] + x1 * w1[o];
            }
            #pragma unroll
            for (int o = 0; o < 16; o++) {
                pm[o] += __shfl_xor_sync(0xffffffffu, pm[o], 1);
                pm[o] += __shfl_xor_sync(0xffffffffu, pm[o], 2);
            }
            #pragma unroll
            for (int j = 0; j < 4; j++)
                spm[cw * 1024 + r * 16 + qid * 4 + j] = pm[qid * 4 + j];
        }
    }
    __syncthreads();
    #pragma unroll
    for (int j = 0; j < 4; j++) {
        const int e = tid + j * 256;
        const int r = e >> 4, o = e & 15;
        spmT[e] = spm[r * 16 + o] + spm[1024 + r * 16 + o]
                + spm[2048 + r * 16 + o] + spm[3072 + r * 16 + o] + spb2[o];
    }
    __syncthreads();
    {
        const int r = tid >> 2;
        const int zb = (tid & 3) * 32;
        const int rc = srcv[r];
        const float* vr = g_vij + (size_t)(e0 + r) * 128;
        #pragma unroll
        for (int z = zb; z < zb + 32; z += 4) {
            float4 vv = *(const float4*)(vr + z);
            float p = spmT[r * 16 + (z >> 3)];
            red_add_v4(&g_paggr[(size_t)rc * 128 + z],
                       vv.x * p, vv.y * p, vv.z * p, vv.w * p);
        }
    }
}

// ---------------- kernel: per-node update ----------------
__global__ __launch_bounds__(128) void node_kernel(
    const float* __restrict__ s, const float* __restrict__ v,
    const float* __restrict__ U1, const float* __restrict__ ub1,
    const float* __restrict__ U2, const float* __restrict__ ub2,
    const float* __restrict__ gl_w, const float* __restrict__ gl_b,
    const float* __restrict__ gr_w, const float* __restrict__ gr_b,
    const float* __restrict__ go_w, const float* __restrict__ go_b,
    const float* __restrict__ ln_a,
    float* __restrict__ out_s, float* __restrict__ out_v)
{
    __shared__ __align__(16) float y[TN][256];
    __shared__ __align__(16) float h[TN][128];
    __shared__ __align__(16) float p[TN][128];
    __shared__ __align__(16) float vo[TN][128];
    __shared__ float cn[TN][16];
    __shared__ float nrm[TN];
    __shared__ float dinv[TN];
    __shared__ float wl[1024], wr[1024], wo[2048];
    __shared__ float wlb[16], wrb[16], wob[16], lna[16];

    const int tid = threadIdx.x;
    const int n0 = blockIdx.x * TN;

    for (int i = tid; i < 1024; i += 128) { wl[i] = gl_w[i]; wr[i] = gr_w[i]; }
    for (int i = tid; i < 2048; i += 128) wo[i] = go_w[i];
    if (tid < 16) { wlb[tid] = gl_b[tid]; wrb[tid] = gr_b[tid];
                    wob[tid] = go_b[tid]; lna[tid] = ln_a[tid]; }
    if (tid < TN) dinv[tid] = rsqrtf(g_deg[n0 + tid]);
    __syncthreads();

    for (int idx = tid; idx < TN * 128; idx += 128) {
        int n = idx >> 7, c = idx & 127;
        y[n][c]       = s[(n0 + n) * 128 + c];
        y[n][128 + c] = g_maggr[(n0 + n) * 128 + c] * dinv[n];
        p[n][c]       = g_paggr[(n0 + n) * 128 + c] * dinv[n];
    }
    __syncthreads();

    {
        float acc[TN];
        float bb = ub1[tid];
        #pragma unroll
        for (int n = 0; n < TN; n++) acc[n] = bb;
        for (int k = 0; k < 256; k += 4) {
            float w0 = U1[(k + 0) * 128 + tid];
            float w1 = U1[(k + 1) * 128 + tid];
            float w2 = U1[(k + 2) * 128 + tid];
            float w3 = U1[(k + 3) * 128 + tid];
            #pragma unroll
            for (int n = 0; n < TN; n++) {
                float4 x = *(const float4*)&y[n][k];
                acc[n] += x.x * w0 + x.y * w1 + x.z * w2 + x.w * w3;
            }
        }
        #pragma unroll
        for (int n = 0; n < TN; n++) h[n][tid] = fmaxf(acc[n], 0.f);
    }
    __syncthreads();

    {
        float acc[TN];
        float bb = ub2[tid];
        #pragma unroll
        for (int n = 0; n < TN; n++) acc[n] = bb;
        for (int k = 0; k < 128; k += 4) {
            float w0 = U2[(k + 0) * 128 + tid];
            float w1 = U2[(k + 1) * 128 + tid];
            float w2 = U2[(k + 2) * 128 + tid];
            float w3 = U2[(k + 3) * 128 + tid];
            #pragma unroll
            for (int n = 0; n < TN; n++) {
                float4 x = *(const float4*)&h[n][k];
                acc[n] += x.x * w0 + x.y * w1 + x.z * w2 + x.w * w3;
            }
        }
        #pragma unroll
        for (int n = 0; n < TN; n++)
            out_s[(n0 + n) * 128 + tid] = y[n][tid] + acc[n];
    }
    __syncthreads();

    for (int idx = tid; idx < TN * 128; idx += 128) {
        int n = idx >> 7, z = idx & 127, o = z >> 3, bl = z & 7;
        int g = c_grade[bl];
        float al = (bl == 0) ? wlb[o] : 0.f;
        float ar = (bl == 0) ? wrb[o] : 0.f;
        #pragma unroll
        for (int c = 0; c < 16; c++) {
            float pv = p[n][c * 8 + bl];
            al += pv * wl[o * 64 + c * 4 + g];
            ar += pv * wr[o * 64 + c * 4 + g];
        }
        y[n][z] = al;
        y[n][128 + z] = ar;
    }
    __syncthreads();

    for (int idx = tid; idx < TN * 16; idx += 128) {
        int n = idx >> 4, c = idx & 15;
        float a[8], b[8], o8[8];
        #pragma unroll
        for (int i = 0; i < 8; i++) {
            a[i] = y[n][c * 8 + i];
            b[i] = y[n][128 + c * 8 + i];
            o8[i] = 0.f;
        }
        #pragma unroll
        for (int i = 0; i < 8; i++)
            #pragma unroll
            for (int j = 0; j < 8; j++)
                o8[RES[i][j]] += SGN[i][j] * a[i] * b[j];
        #pragma unroll
        for (int k = 0; k < 8; k++) h[n][c * 8 + k] = o8[k];
    }
    __syncthreads();

    for (int idx = tid; idx < TN * 128; idx += 128) {
        int n = idx >> 7, z = idx & 127, o = z >> 3, bl = z & 7;
        int g = c_grade[bl];
        float acc = (bl == 0) ? wob[o] : 0.f;
        #pragma unroll
        for (int c = 0; c < 16; c++)
            acc += h[n][c * 8 + bl] * wo[o * 128 + c * 4 + g];
        #pragma unroll
        for (int c = 0; c < 16; c++)
            acc += p[n][c * 8 + bl] * wo[o * 128 + (16 + c) * 4 + g];
        vo[n][z] = acc;
    }
    __syncthreads();

    for (int idx = tid; idx < TN * 16; idx += 128) {
        int n = idx >> 4, c = idx & 15;
        float acc = 0.f;
        #pragma unroll
        for (int bl = 0; bl < 8; bl++) { float x = vo[n][c * 8 + bl]; acc += x * x; }
        cn[n][c] = sqrtf(acc);
    }
    __syncthreads();
    if (tid < TN) {
        float acc = 0.f;
        #pragma unroll
        for (int c = 0; c < 16; c++) acc += cn[tid][c];
        nrm[tid] = acc * (1.f / 16.f) + 1e-6f;
    }
    __syncthreads();
    for (int idx = tid; idx < TN * 128; idx += 128) {
        int n = idx >> 7, z = idx & 127, c = z >> 3;
        out_v[(n0 + n) * 128 + z] = lna[c] * vo[n][z] / nrm[n] + v[(n0 + n) * 128 + z];
    }
}

// ---------------- launcher ----------------
extern "C" void kernel_launch(void* const* d_in, const int* in_sizes, int n_in,
                              void* d_out, int out_size) {
    const float* s     = (const float*)d_in[0];
    const float* v     = (const float*)d_in[1];
    const int*   ei    = (const int*)  d_in[2];
    const float* Wv_w  = (const float*)d_in[3];
    const float* Wv_b  = (const float*)d_in[4];
    const float* mn_W1 = (const float*)d_in[5];
    const float* mn_b1 = (const float*)d_in[6];
    const float* mn_W2 = (const float*)d_in[7];
    const float* mn_b2 = (const float*)d_in[8];
    const float* pn_W1 = (const float*)d_in[9];
    const float* pn_b1 = (const float*)d_in[10];
    const float* pn_W2 = (const float*)d_in[11];
    const float* pn_b2 = (const float*)d_in[12];
    const float* un_W1 = (const float*)d_in[13];
    const float* un_b1 = (const float*)d_in[14];
    const float* un_W2 = (const float*)d_in[15];
    const float* un_b2 = (const float*)d_in[16];
    const float* gl_w  = (const float*)d_in[17];
    const float* gl_b  = (const float*)d_in[18];
    const float* gr_w  = (const float*)d_in[19];
    const float* gr_b  = (const float*)d_in[20];
    const float* go_w  = (const float*)d_in[21];
    const float* go_b  = (const float*)d_in[22];
    const float* ln_a  = (const float*)d_in[23];
    float* out = (float*)d_out;

    cudaFuncSetAttribute(fused_gemm_kernel,
                         cudaFuncAttributeMaxDynamicSharedMemorySize, FUSED_SMEM);

    zero_kernel<<<2048, 256>>>();
    prep_kernel<<<2048, 256>>>(s, mn_W1, mn_W2, pn_W1);
    edge_pre_kernel<<<Ee / TBE, 128>>>(v, ei, Wv_w, Wv_b);
    fused_gemm_kernel<<<Ee / 64, 256, FUSED_SMEM>>>(ei, mn_b1, mn_b2, pn_b1, pn_W2, pn_b2);
    node_kernel<<<Nn / TN, 128>>>(s, v, un_W1, un_b1, un_W2, un_b2,
                                  gl_w, gl_b, gr_w, gr_b, go_w, go_b, ln_a,
                                  out, out + Nn * 128);
}